// round 1
// baseline (speedup 1.0000x reference)
#include <cuda_runtime.h>
#include <cuda_bf16.h>

#define NN 50000
#define NE 800000
#define INC 165
#define HID 256
#define OUTC 2

// Scratch (static device globals — no runtime allocation allowed)
__device__ float g_agg1[(size_t)NN * INC];
__device__ float g_h1[(size_t)NN * HID];
__device__ float g_h[(size_t)NN * HID];
__device__ float g_agg2[(size_t)NN * HID];
__device__ float g_t[(size_t)NN * HID];

// ---------------------------------------------------------------------------
// Scatter-add: agg[dst] += feat[src] over edges. One warp per edge.
// ---------------------------------------------------------------------------
__global__ void scatter_add_kernel(const float* __restrict__ feat,
                                   const int* __restrict__ src,
                                   const int* __restrict__ dst,
                                   float* __restrict__ agg,
                                   int nE, int C) {
    int e = blockIdx.x * (blockDim.x >> 5) + (threadIdx.x >> 5);
    if (e >= nE) return;
    int s = __ldg(src + e);
    int d = __ldg(dst + e);
    const float* fs = feat + (size_t)s * C;
    float* ad = agg + (size_t)d * C;
    for (int c = (threadIdx.x & 31); c < C; c += 32)
        atomicAdd(ad + c, __ldg(fs + c));
}

// ---------------------------------------------------------------------------
// Tiled fp32 GEMM: C[M,N] = act( (A (+A2)) @ W[K,N] + bias )
// BM=128, BN=64, BK=16, 256 threads, 8x4 per-thread micro-tile.
// ---------------------------------------------------------------------------
template<bool FUSE_ADD, bool RELU>
__global__ __launch_bounds__(256)
void gemm_kernel(const float* __restrict__ A,
                 const float* __restrict__ A2,
                 const float* __restrict__ W,
                 const float* __restrict__ bias,
                 float* __restrict__ C,
                 int M, int N, int K) {
    constexpr int BM = 128, BN = 64, BK = 16;
    __shared__ __align__(16) float As[BK][BM];
    __shared__ __align__(16) float Bs[BK][BN];

    const int tid = threadIdx.x;
    const int tx = tid & 15;      // N direction (16)
    const int ty = tid >> 4;      // M direction (16)
    const int bm0 = blockIdx.y * BM;
    const int bn0 = blockIdx.x * BN;

    float acc[8][4];
#pragma unroll
    for (int i = 0; i < 8; i++)
#pragma unroll
        for (int j = 0; j < 4; j++) acc[i][j] = 0.f;

    // A-tile load mapping: 2 threads per row, 8 consecutive k each
    const int aRow = tid >> 1;          // 0..127
    const int aK   = (tid & 1) * 8;     // 0 or 8
    // B-tile load mapping: 16 threads per k-row, float4 each
    const int bRow = tid >> 4;          // 0..15
    const int bCol = (tid & 15) * 4;    // 0..60

    for (int k0 = 0; k0 < K; k0 += BK) {
        // --- load A tile (transposed into As[k][m]) ---
        {
            const int gRow = bm0 + aRow;
            const bool rowOk = (gRow < M);
            const size_t base = (size_t)gRow * K;
#pragma unroll
            for (int j = 0; j < 8; j++) {
                const int gk = k0 + aK + j;
                float v = 0.f;
                if (rowOk && gk < K) {
                    v = A[base + gk];
                    if (FUSE_ADD) v += A2[base + gk];
                }
                As[aK + j][aRow] = v;
            }
        }
        // --- load B tile ---
        {
            const int gk = k0 + bRow;
            float4 v = make_float4(0.f, 0.f, 0.f, 0.f);
            if (gk < K)
                v = *reinterpret_cast<const float4*>(&W[(size_t)gk * N + bn0 + bCol]);
            *reinterpret_cast<float4*>(&Bs[bRow][bCol]) = v;
        }
        __syncthreads();

#pragma unroll
        for (int kk = 0; kk < BK; kk++) {
            const float4 a0 = *reinterpret_cast<const float4*>(&As[kk][ty * 8]);
            const float4 a1 = *reinterpret_cast<const float4*>(&As[kk][ty * 8 + 4]);
            const float4 bv = *reinterpret_cast<const float4*>(&Bs[kk][tx * 4]);
            const float a[8] = {a0.x, a0.y, a0.z, a0.w, a1.x, a1.y, a1.z, a1.w};
            const float b[4] = {bv.x, bv.y, bv.z, bv.w};
#pragma unroll
            for (int i = 0; i < 8; i++)
#pragma unroll
                for (int j = 0; j < 4; j++)
                    acc[i][j] = fmaf(a[i], b[j], acc[i][j]);
        }
        __syncthreads();
    }

    // --- epilogue: bias (+ relu), float4 stores ---
    const float4 bb = *reinterpret_cast<const float4*>(&bias[bn0 + tx * 4]);
#pragma unroll
    for (int i = 0; i < 8; i++) {
        const int row = bm0 + ty * 8 + i;
        if (row < M) {
            float4 o;
            o.x = acc[i][0] + bb.x;
            o.y = acc[i][1] + bb.y;
            o.z = acc[i][2] + bb.z;
            o.w = acc[i][3] + bb.w;
            if (RELU) {
                o.x = fmaxf(o.x, 0.f); o.y = fmaxf(o.y, 0.f);
                o.z = fmaxf(o.z, 0.f); o.w = fmaxf(o.w, 0.f);
            }
            *reinterpret_cast<float4*>(&C[(size_t)row * N + bn0 + tx * 4]) = o;
        }
    }
}

// ---------------------------------------------------------------------------
// Final tiny GEMM: out[M,2] = T[M,256] @ W[256,2] + b. One warp per row.
// ---------------------------------------------------------------------------
__global__ void out_gemv_kernel(const float* __restrict__ T,
                                const float* __restrict__ W,
                                const float* __restrict__ b,
                                float* __restrict__ out, int M) {
    int row = blockIdx.x * (blockDim.x >> 5) + (threadIdx.x >> 5);
    if (row >= M) return;
    const int lane = threadIdx.x & 31;
    const float* tr = T + (size_t)row * HID;
    float s0 = 0.f, s1 = 0.f;
#pragma unroll
    for (int k = lane; k < HID; k += 32) {
        const float t = tr[k];
        s0 = fmaf(t, __ldg(&W[k * 2 + 0]), s0);
        s1 = fmaf(t, __ldg(&W[k * 2 + 1]), s1);
    }
#pragma unroll
    for (int off = 16; off; off >>= 1) {
        s0 += __shfl_down_sync(0xffffffffu, s0, off);
        s1 += __shfl_down_sync(0xffffffffu, s1, off);
    }
    if (lane == 0) {
        out[(size_t)row * 2 + 0] = s0 + b[0];
        out[(size_t)row * 2 + 1] = s1 + b[1];
    }
}

// ---------------------------------------------------------------------------
extern "C" void kernel_launch(void* const* d_in, const int* in_sizes, int n_in,
                              void* d_out, int out_size) {
    const float* x   = (const float*)d_in[0];
    const int*   ei  = (const int*)d_in[1];
    const float* W1a = (const float*)d_in[2];
    const float* b1a = (const float*)d_in[3];
    const float* W1b = (const float*)d_in[4];
    const float* b1b = (const float*)d_in[5];
    const float* W2a = (const float*)d_in[6];
    const float* b2a = (const float*)d_in[7];
    const float* W2b = (const float*)d_in[8];
    const float* b2b = (const float*)d_in[9];
    float* out = (float*)d_out;

    const int* src = ei;            // edge_index[0]
    const int* dst = ei + NE;       // edge_index[1]

    float *agg1, *h1, *h, *agg2, *t;
    cudaGetSymbolAddress((void**)&agg1, g_agg1);
    cudaGetSymbolAddress((void**)&h1,   g_h1);
    cudaGetSymbolAddress((void**)&h,    g_h);
    cudaGetSymbolAddress((void**)&agg2, g_agg2);
    cudaGetSymbolAddress((void**)&t,    g_t);

    const dim3 gemmGrid((HID + 63) / 64, (NN + 127) / 128);
    const int scatterGrid = (NE + 7) / 8;       // 8 warps/block
    const int gemvGrid = (NN + 7) / 8;

    // Layer 1: agg over x (C=165)
    cudaMemsetAsync(agg1, 0, sizeof(float) * (size_t)NN * INC);
    scatter_add_kernel<<<scatterGrid, 256>>>(x, src, dst, agg1, NE, INC);
    // h1 = relu((x + agg1) @ W1a + b1a)
    gemm_kernel<true, true><<<gemmGrid, 256>>>(x, agg1, W1a, b1a, h1, NN, HID, INC);
    // h = relu(h1 @ W1b + b1b)   (GIN output + outer relu fused)
    gemm_kernel<false, true><<<gemmGrid, 256>>>(h1, nullptr, W1b, b1b, h, NN, HID, HID);

    // Layer 2: agg over h (C=256)
    cudaMemsetAsync(agg2, 0, sizeof(float) * (size_t)NN * HID);
    scatter_add_kernel<<<scatterGrid, 256>>>(h, src, dst, agg2, NE, HID);
    // t = relu((h + agg2) @ W2a + b2a)
    gemm_kernel<true, true><<<gemmGrid, 256>>>(h, agg2, W2a, b2a, t, NN, HID, HID);
    // out = t @ W2b + b2b
    out_gemv_kernel<<<gemvGrid, 256>>>(t, W2b, b2b, out, NN);
}

// round 4
// speedup vs baseline: 1.4893x; 1.4893x over previous
#include <cuda_runtime.h>
#include <cuda_bf16.h>
#include <cstdint>

#define NN 50000
#define NE 800000
#define INC 165
#define HID 256
#define OUTC 2
#define AGG1_LD 168          // padded stride so float4 atomics are 16B-aligned
#define KP1 192              // K=165 padded to multiple of 64

// ---------------- scratch (no runtime allocation allowed) ----------------
__device__ float g_agg1[(size_t)NN * AGG1_LD];
__device__ float g_h1[(size_t)NN * HID];
__device__ float g_h[(size_t)NN * HID];
__device__ float g_agg2[(size_t)NN * HID];
__device__ float g_t[(size_t)NN * HID];
__device__ __nv_bfloat16 g_w1a_hi[HID * KP1];
__device__ __nv_bfloat16 g_w1a_lo[HID * KP1];
__device__ __nv_bfloat16 g_w1b_hi[HID * HID];
__device__ __nv_bfloat16 g_w1b_lo[HID * HID];
__device__ __nv_bfloat16 g_w2a_hi[HID * HID];
__device__ __nv_bfloat16 g_w2a_lo[HID * HID];

// ---------------- PTX helpers ----------------
__device__ __forceinline__ uint32_t smem_u32(const void* p) {
    uint32_t a;
    asm("{ .reg .u64 t; cvta.to.shared.u64 t, %1; cvt.u32.u64 %0, t; }" : "=r"(a) : "l"(p));
    return a;
}
__device__ __forceinline__ void ldm_x4(uint32_t* r, uint32_t addr) {
    asm volatile("ldmatrix.sync.aligned.m8n8.x4.shared.b16 {%0,%1,%2,%3}, [%4];"
        : "=r"(r[0]), "=r"(r[1]), "=r"(r[2]), "=r"(r[3]) : "r"(addr));
}
__device__ __forceinline__ void ldm_x2(uint32_t* r, uint32_t addr) {
    asm volatile("ldmatrix.sync.aligned.m8n8.x2.shared.b16 {%0,%1}, [%2];"
        : "=r"(r[0]), "=r"(r[1]) : "r"(addr));
}
__device__ __forceinline__ void mma_bf16(float* c, const uint32_t* a, const uint32_t* b) {
    asm volatile("mma.sync.aligned.m16n8k16.row.col.f32.bf16.bf16.f32 "
        "{%0,%1,%2,%3}, {%4,%5,%6,%7}, {%8,%9}, {%0,%1,%2,%3};"
        : "+f"(c[0]), "+f"(c[1]), "+f"(c[2]), "+f"(c[3])
        : "r"(a[0]), "r"(a[1]), "r"(a[2]), "r"(a[3]), "r"(b[0]), "r"(b[1]));
}
__device__ __forceinline__ uint32_t pack2(float v0, float v1) {
    __nv_bfloat162 h = __floats2bfloat162_rn(v0, v1);   // x=v0 (low), y=v1 (high)
    return *(uint32_t*)&h;
}

// ---------------------------------------------------------------------------
// Scatter-add, vectorized atomics. One warp per edge.
// ---------------------------------------------------------------------------
__global__ void scatter1_kernel(const float* __restrict__ x,
                                const int* __restrict__ src,
                                const int* __restrict__ dst,
                                float* __restrict__ agg, int nE) {
    int e = blockIdx.x * (blockDim.x >> 5) + (threadIdx.x >> 5);
    if (e >= nE) return;
    int s = __ldg(src + e), d = __ldg(dst + e);
    const float* fs = x + (size_t)s * INC;
    float* ad = agg + (size_t)d * AGG1_LD;
    int lane = threadIdx.x & 31;
    for (int g = lane; g < 41; g += 32) {
        int c = g * 4;
        float v0 = __ldg(fs + c), v1 = __ldg(fs + c + 1);
        float v2 = __ldg(fs + c + 2), v3 = __ldg(fs + c + 3);
        asm volatile("red.global.add.v4.f32 [%0], {%1,%2,%3,%4};"
                     :: "l"(ad + c), "f"(v0), "f"(v1), "f"(v2), "f"(v3) : "memory");
    }
    if (lane == 0) atomicAdd(ad + 164, __ldg(fs + 164));
}

__global__ void scatter2_kernel(const float* __restrict__ h,
                                const int* __restrict__ src,
                                const int* __restrict__ dst,
                                float* __restrict__ agg, int nE) {
    int e = blockIdx.x * (blockDim.x >> 5) + (threadIdx.x >> 5);
    if (e >= nE) return;
    int s = __ldg(src + e), d = __ldg(dst + e);
    const float4* fs4 = (const float4*)(h + (size_t)s * HID);
    float* ad = agg + (size_t)d * HID;
    int lane = threadIdx.x & 31;
#pragma unroll
    for (int i = 0; i < 2; i++) {
        int g = lane + i * 32;
        float4 v = __ldg(fs4 + g);
        asm volatile("red.global.add.v4.f32 [%0], {%1,%2,%3,%4};"
                     :: "l"(ad + g * 4), "f"(v.x), "f"(v.y), "f"(v.z), "f"(v.w) : "memory");
    }
}

// ---------------------------------------------------------------------------
// Weight prep: W[K,N] fp32 -> W^T split to bf16 hi/lo, [N][Kp], zero-padded.
// ---------------------------------------------------------------------------
__global__ void prep_w_kernel(const float* __restrict__ W,
                              __nv_bfloat16* __restrict__ hi,
                              __nv_bfloat16* __restrict__ lo,
                              int K, int N, int Kp) {
    int i = blockIdx.x * blockDim.x + threadIdx.x;
    if (i >= N * Kp) return;
    int n = i / Kp, k = i % Kp;
    float w = (k < K) ? __ldg(&W[(size_t)k * N + n]) : 0.f;
    __nv_bfloat16 h = __float2bfloat16(w);
    hi[i] = h;
    lo[i] = __float2bfloat16(w - __bfloat162float(h));
}

// ---------------------------------------------------------------------------
// Warp-MMA bf16-split GEMM: C[M,256] = relu((A (+A2)) @ W + bias)
// CTA tile 128x128, grid (2, ceil(M/128)). 8 warps: 4M x 2N, warp tile 32x64.
// Smem: A/B hi+lo, rows padded to 72 bf16 (144B).
// ---------------------------------------------------------------------------
#define SROW 72
#define SMAT (128 * SROW * 2)      // 18432 B per matrix
#define OFF_AHI 0
#define OFF_ALO (SMAT)
#define OFF_BHI (2 * SMAT)
#define OFF_BLO (3 * SMAT)
#define SMTOT (4 * SMAT)           // 73728 B

template<bool FUSE, bool RELU, bool VEC>
__global__ __launch_bounds__(256)
void mma_gemm_kernel(const float* __restrict__ A, int lda,
                     const float* __restrict__ A2, int lda2,
                     const __nv_bfloat16* __restrict__ Bh,
                     const __nv_bfloat16* __restrict__ Bl, int Kp,
                     const float* __restrict__ bias,
                     float* __restrict__ C, int M, int K) {
    extern __shared__ __align__(16) char smem[];
    const uint32_t sb = smem_u32(smem);
    const int tid = threadIdx.x, wid = tid >> 5, lane = tid & 31;

    const int bm0 = blockIdx.y * 128;
    const int n0 = blockIdx.x * 128;

    // loader mapping: thread -> (row tid>>1, 32 cols at (tid&1)*32)
    const int arow = tid >> 1;
    const int acol0 = (tid & 1) * 32;

    // warp tile: mw in {0,32,64,96}, nw in {0,64}
    const int mw = (wid >> 1) * 32;
    const int nw = (wid & 1) * 64;

    float acc[2][8][4];
#pragma unroll
    for (int ms = 0; ms < 2; ms++)
#pragma unroll
        for (int ns = 0; ns < 8; ns++)
#pragma unroll
            for (int q = 0; q < 4; q++) acc[ms][ns][q] = 0.f;

    // ldmatrix lane address components
    const int l7 = lane & 7;
    const int aRowAdd = ((lane >> 3) & 1) * 8;   // +8 rows for groups 1,3
    const int aKAdd = (lane >> 4) * 8;           // +8 k for groups 2,3
    const int bl = lane & 15;
    const int bRow = bl & 7;
    const int bKAdd = ((bl >> 3) & 1) * 8;

    const int nchunks = Kp >> 6;
    for (int ch = 0; ch < nchunks; ch++) {
        const int k0 = ch << 6;

        // ---- fill A hi/lo smem tile [128][64] ----
        {
            const int gRow = bm0 + arow;
            const bool ok = gRow < M;
            const uint32_t so = (uint32_t)(arow * SROW + acol0) * 2;
            if (VEC && ok) {
                const float4* p = (const float4*)(A + (size_t)gRow * lda + k0 + acol0);
                const float4* p2 = FUSE ? (const float4*)(A2 + (size_t)gRow * lda2 + k0 + acol0) : nullptr;
#pragma unroll
                for (int q = 0; q < 8; q++) {
                    float4 v = __ldg(p + q);
                    if (FUSE) {
                        float4 w = __ldg(p2 + q);
                        v.x += w.x; v.y += w.y; v.z += w.z; v.w += w.w;
                    }
                    float hx = __bfloat162float(__float2bfloat16(v.x));
                    float hy = __bfloat162float(__float2bfloat16(v.y));
                    float hz = __bfloat162float(__float2bfloat16(v.z));
                    float hw = __bfloat162float(__float2bfloat16(v.w));
                    *(uint32_t*)(smem + OFF_AHI + so + q * 8 + 0) = pack2(v.x, v.y);
                    *(uint32_t*)(smem + OFF_AHI + so + q * 8 + 4) = pack2(v.z, v.w);
                    *(uint32_t*)(smem + OFF_ALO + so + q * 8 + 0) = pack2(v.x - hx, v.y - hy);
                    *(uint32_t*)(smem + OFF_ALO + so + q * 8 + 4) = pack2(v.z - hz, v.w - hw);
                }
            } else {
                const float* ar  = A + (size_t)(ok ? gRow : 0) * lda;
                const float* ar2 = FUSE ? (A2 + (size_t)(ok ? gRow : 0) * lda2) : nullptr;
#pragma unroll
                for (int j = 0; j < 32; j += 2) {
                    const int gk0 = k0 + acol0 + j, gk1 = gk0 + 1;
                    float v0 = 0.f, v1 = 0.f;
                    if (ok) {
                        if (gk0 < K) { v0 = __ldg(ar + gk0); if (FUSE) v0 += __ldg(ar2 + gk0); }
                        if (gk1 < K) { v1 = __ldg(ar + gk1); if (FUSE) v1 += __ldg(ar2 + gk1); }
                    }
                    float h0 = __bfloat162float(__float2bfloat16(v0));
                    float h1 = __bfloat162float(__float2bfloat16(v1));
                    *(uint32_t*)(smem + OFF_AHI + so + j * 2) = pack2(v0, v1);
                    *(uint32_t*)(smem + OFF_ALO + so + j * 2) = pack2(v0 - h0, v1 - h1);
                }
            }
        }
        // ---- fill B hi/lo smem tile [128 n][64 k] from W^T [N][Kp] ----
        {
            const int n = arow;                      // local n row
            const int gN = n0 + n;
            const uint32_t so = (uint32_t)(n * SROW + acol0) * 2;
            const uint4* ph = (const uint4*)(Bh + (size_t)gN * Kp + k0 + acol0);
            const uint4* pl = (const uint4*)(Bl + (size_t)gN * Kp + k0 + acol0);
#pragma unroll
            for (int q = 0; q < 4; q++) {
                *(uint4*)(smem + OFF_BHI + so + q * 16) = __ldg(ph + q);
                *(uint4*)(smem + OFF_BLO + so + q * 16) = __ldg(pl + q);
            }
        }
        __syncthreads();

        // ---- MMA over 4 k16 steps, 3 split terms ----
#pragma unroll
        for (int kk = 0; kk < 64; kk += 16) {
            uint32_t ahi[2][4], alo[2][4], bhi[8][2], blo[8][2];
#pragma unroll
            for (int ms = 0; ms < 2; ms++) {
                uint32_t ra = sb + (uint32_t)((mw + ms * 16 + l7 + aRowAdd) * SROW + kk + aKAdd) * 2;
                ldm_x4(ahi[ms], ra + OFF_AHI);
                ldm_x4(alo[ms], ra + OFF_ALO);
            }
#pragma unroll
            for (int ns = 0; ns < 8; ns++) {
                uint32_t rb = sb + (uint32_t)((nw + ns * 8 + bRow) * SROW + kk + bKAdd) * 2;
                ldm_x2(bhi[ns], rb + OFF_BHI);
                ldm_x2(blo[ns], rb + OFF_BLO);
            }
#pragma unroll
            for (int ms = 0; ms < 2; ms++)
#pragma unroll
                for (int ns = 0; ns < 8; ns++) {
                    mma_bf16(acc[ms][ns], ahi[ms], bhi[ns]);
                    mma_bf16(acc[ms][ns], alo[ms], bhi[ns]);
                    mma_bf16(acc[ms][ns], ahi[ms], blo[ns]);
                }
        }
        __syncthreads();
    }

    // ---- epilogue: bias + relu, float2 stores ----
    const int r = lane >> 2;
    const int cp = (lane & 3) * 2;
#pragma unroll
    for (int ms = 0; ms < 2; ms++) {
#pragma unroll
        for (int ns = 0; ns < 8; ns++) {
            const int col = n0 + nw + ns * 8 + cp;
            const float2 bb = *(const float2*)(bias + col);
            const int row0 = bm0 + mw + ms * 16 + r;
            float2 o0, o1;
            o0.x = acc[ms][ns][0] + bb.x; o0.y = acc[ms][ns][1] + bb.y;
            o1.x = acc[ms][ns][2] + bb.x; o1.y = acc[ms][ns][3] + bb.y;
            if (RELU) {
                o0.x = fmaxf(o0.x, 0.f); o0.y = fmaxf(o0.y, 0.f);
                o1.x = fmaxf(o1.x, 0.f); o1.y = fmaxf(o1.y, 0.f);
            }
            if (row0 < M)     *(float2*)(C + (size_t)row0 * HID + col) = o0;
            if (row0 + 8 < M) *(float2*)(C + (size_t)(row0 + 8) * HID + col) = o1;
        }
    }
}

// ---------------------------------------------------------------------------
// Final 256->2 projection: out[M,2] = T @ W2b + b2b. One warp per row.
// ---------------------------------------------------------------------------
__global__ void out_gemv_kernel(const float* __restrict__ T,
                                const float* __restrict__ W,
                                const float* __restrict__ b,
                                float* __restrict__ out, int M) {
    int row = blockIdx.x * (blockDim.x >> 5) + (threadIdx.x >> 5);
    if (row >= M) return;
    const int lane = threadIdx.x & 31;
    const float* tr = T + (size_t)row * HID;
    float s0 = 0.f, s1 = 0.f;
#pragma unroll
    for (int k = lane; k < HID; k += 32) {
        const float t = __ldg(tr + k);
        s0 = fmaf(t, __ldg(&W[k * 2 + 0]), s0);
        s1 = fmaf(t, __ldg(&W[k * 2 + 1]), s1);
    }
#pragma unroll
    for (int off = 16; off; off >>= 1) {
        s0 += __shfl_down_sync(0xffffffffu, s0, off);
        s1 += __shfl_down_sync(0xffffffffu, s1, off);
    }
    if (lane == 0) {
        out[(size_t)row * 2 + 0] = s0 + __ldg(b + 0);
        out[(size_t)row * 2 + 1] = s1 + __ldg(b + 1);
    }
}

// ---------------------------------------------------------------------------
extern "C" void kernel_launch(void* const* d_in, const int* in_sizes, int n_in,
                              void* d_out, int out_size) {
    const float* x   = (const float*)d_in[0];
    const int*   ei  = (const int*)d_in[1];
    const float* W1a = (const float*)d_in[2];
    const float* b1a = (const float*)d_in[3];
    const float* W1b = (const float*)d_in[4];
    const float* b1b = (const float*)d_in[5];
    const float* W2a = (const float*)d_in[6];
    const float* b2a = (const float*)d_in[7];
    const float* W2b = (const float*)d_in[8];
    const float* b2b = (const float*)d_in[9];
    float* out = (float*)d_out;

    const int* src = ei;
    const int* dst = ei + NE;

    float *agg1, *h1, *h, *agg2, *t;
    __nv_bfloat16 *w1ah, *w1al, *w1bh, *w1bl, *w2ah, *w2al;
    cudaGetSymbolAddress((void**)&agg1, g_agg1);
    cudaGetSymbolAddress((void**)&h1,   g_h1);
    cudaGetSymbolAddress((void**)&h,    g_h);
    cudaGetSymbolAddress((void**)&agg2, g_agg2);
    cudaGetSymbolAddress((void**)&t,    g_t);
    cudaGetSymbolAddress((void**)&w1ah, g_w1a_hi);
    cudaGetSymbolAddress((void**)&w1al, g_w1a_lo);
    cudaGetSymbolAddress((void**)&w1bh, g_w1b_hi);
    cudaGetSymbolAddress((void**)&w1bl, g_w1b_lo);
    cudaGetSymbolAddress((void**)&w2ah, g_w2a_hi);
    cudaGetSymbolAddress((void**)&w2al, g_w2a_lo);

    cudaFuncSetAttribute(mma_gemm_kernel<true,  true, false>,
                         cudaFuncAttributeMaxDynamicSharedMemorySize, SMTOT);
    cudaFuncSetAttribute(mma_gemm_kernel<false, true, true>,
                         cudaFuncAttributeMaxDynamicSharedMemorySize, SMTOT);
    cudaFuncSetAttribute(mma_gemm_kernel<true,  true, true>,
                         cudaFuncAttributeMaxDynamicSharedMemorySize, SMTOT);

    const dim3 gemmGrid(2, (NN + 127) / 128);   // N=256 in two 128-col halves
    const int scatterGrid = (NE + 7) / 8;
    const int gemvGrid = (NN + 7) / 8;

    // ---- weight prep (all layers up front) ----
    prep_w_kernel<<<(HID * KP1 + 255) / 256, 256>>>(W1a, w1ah, w1al, INC, HID, KP1);
    prep_w_kernel<<<(HID * HID + 255) / 256, 256>>>(W1b, w1bh, w1bl, HID, HID, HID);
    prep_w_kernel<<<(HID * HID + 255) / 256, 256>>>(W2a, w2ah, w2al, HID, HID, HID);

    // ---- layer 1 ----
    cudaMemsetAsync(agg1, 0, sizeof(float) * (size_t)NN * AGG1_LD);
    scatter1_kernel<<<scatterGrid, 256>>>(x, src, dst, agg1, NE);
    mma_gemm_kernel<true, true, false><<<gemmGrid, 256, SMTOT>>>(
        x, INC, agg1, AGG1_LD, w1ah, w1al, KP1, b1a, h1, NN, INC);
    mma_gemm_kernel<false, true, true><<<gemmGrid, 256, SMTOT>>>(
        h1, HID, nullptr, 0, w1bh, w1bl, HID, b1b, h, NN, HID);

    // ---- layer 2 ----
    cudaMemsetAsync(agg2, 0, sizeof(float) * (size_t)NN * HID);
    scatter2_kernel<<<scatterGrid, 256>>>(h, src, dst, agg2, NE);
    mma_gemm_kernel<true, true, true><<<gemmGrid, 256, SMTOT>>>(
        h, HID, agg2, HID, w2ah, w2al, HID, b2a, t, NN, HID);
    out_gemv_kernel<<<gemvGrid, 256>>>(t, W2b, b2b, out, NN);
}

// round 5
// speedup vs baseline: 2.3162x; 1.5552x over previous
#include <cuda_runtime.h>
#include <cuda_bf16.h>
#include <cstdint>

#define NN 50000
#define NE 800000
#define INC 165
#define HID 256
#define OUTC 2
#define XP_LD 168            // padded x stride (42 float4s)
#define KP1 192              // K=165 padded to multiple of 64

// ---------------- scratch (no runtime allocation allowed) ----------------
__device__ int   g_cnt[NN];
__device__ int   g_ptr[NN + 1];
__device__ int   g_cursor[NN];
__device__ int   g_csr[NE];
__device__ float g_xp[(size_t)NN * XP_LD + 256];
__device__ float g_z1[(size_t)NN * XP_LD + 256];
__device__ float g_h1[(size_t)NN * HID];
__device__ float g_h[(size_t)NN * HID];
__device__ float g_z2[(size_t)NN * HID + 256];
__device__ __nv_bfloat16 g_w1a_hi[HID * KP1];
__device__ __nv_bfloat16 g_w1a_lo[HID * KP1];
__device__ __nv_bfloat16 g_w1b_hi[HID * HID];
__device__ __nv_bfloat16 g_w1b_lo[HID * HID];
__device__ __nv_bfloat16 g_w2a_hi[HID * HID];
__device__ __nv_bfloat16 g_w2a_lo[HID * HID];

// ---------------- PTX helpers ----------------
__device__ __forceinline__ uint32_t smem_u32(const void* p) {
    uint32_t a;
    asm("{ .reg .u64 t; cvta.to.shared.u64 t, %1; cvt.u32.u64 %0, t; }" : "=r"(a) : "l"(p));
    return a;
}
__device__ __forceinline__ void ldm_x4(uint32_t* r, uint32_t addr) {
    asm volatile("ldmatrix.sync.aligned.m8n8.x4.shared.b16 {%0,%1,%2,%3}, [%4];"
        : "=r"(r[0]), "=r"(r[1]), "=r"(r[2]), "=r"(r[3]) : "r"(addr));
}
__device__ __forceinline__ void ldm_x2(uint32_t* r, uint32_t addr) {
    asm volatile("ldmatrix.sync.aligned.m8n8.x2.shared.b16 {%0,%1}, [%2];"
        : "=r"(r[0]), "=r"(r[1]) : "r"(addr));
}
__device__ __forceinline__ void mma_bf16(float* c, const uint32_t* a, const uint32_t* b) {
    asm volatile("mma.sync.aligned.m16n8k16.row.col.f32.bf16.bf16.f32 "
        "{%0,%1,%2,%3}, {%4,%5,%6,%7}, {%8,%9}, {%0,%1,%2,%3};"
        : "+f"(c[0]), "+f"(c[1]), "+f"(c[2]), "+f"(c[3])
        : "r"(a[0]), "r"(a[1]), "r"(a[2]), "r"(a[3]), "r"(b[0]), "r"(b[1]));
}
__device__ __forceinline__ uint32_t pack2(float v0, float v1) {
    __nv_bfloat162 h = __floats2bfloat162_rn(v0, v1);
    return *(uint32_t*)&h;
}

// ---------------------------------------------------------------------------
// CSR build
// ---------------------------------------------------------------------------
__global__ void hist_kernel(const int* __restrict__ dst, int* __restrict__ cnt) {
    int e = blockIdx.x * blockDim.x + threadIdx.x;
    if (e < NE) atomicAdd(&cnt[__ldg(dst + e)], 1);
}

__global__ void scan_kernel(const int* __restrict__ cnt,
                            int* __restrict__ ptr, int* __restrict__ cursor) {
    __shared__ int wsum[32];
    __shared__ int running;
    const int t = threadIdx.x;
    if (t == 0) running = 0;
    __syncthreads();
    for (int base = 0; base < NN; base += 1024) {
        int v = (base + t < NN) ? cnt[base + t] : 0;
        int x = v;
#pragma unroll
        for (int o = 1; o < 32; o <<= 1) {
            int y = __shfl_up_sync(0xffffffffu, x, o);
            if ((t & 31) >= o) x += y;
        }
        if ((t & 31) == 31) wsum[t >> 5] = x;
        __syncthreads();
        if (t < 32) {
            int w = wsum[t];
#pragma unroll
            for (int o = 1; o < 32; o <<= 1) {
                int y = __shfl_up_sync(0xffffffffu, w, o);
                if (t >= o) w += y;
            }
            wsum[t] = w;
        }
        __syncthreads();
        int excl = x - v + ((t >= 32) ? wsum[(t >> 5) - 1] : 0) + running;
        if (base + t < NN) { ptr[base + t] = excl; cursor[base + t] = excl; }
        __syncthreads();
        if (t == 0) running += wsum[31];
        __syncthreads();
    }
    if (t == 0) ptr[NN] = running;
}

__global__ void fill_kernel(const int* __restrict__ src, const int* __restrict__ dst,
                            int* __restrict__ cursor, int* __restrict__ csr) {
    int e = blockIdx.x * blockDim.x + threadIdx.x;
    if (e < NE) {
        int p = atomicAdd(&cursor[__ldg(dst + e)], 1);
        csr[p] = __ldg(src + e);
    }
}

// x [NN][165] -> xp [NN][168] (16B-aligned rows, zero padding)
__global__ void copy_pad_kernel(const float* __restrict__ x, float* __restrict__ xp) {
    int i = blockIdx.x * blockDim.x + threadIdx.x;
    if (i >= NN * XP_LD) return;
    int n = i / XP_LD, c = i % XP_LD;
    xp[i] = (c < INC) ? __ldg(&x[(size_t)n * INC + c]) : 0.f;
}

// ---------------------------------------------------------------------------
// Gather-aggregate: z[n] = feat[n] + sum_{nbr in csr} feat[nbr]. Warp per node.
// ---------------------------------------------------------------------------
__global__ void gather1_kernel(const float4* __restrict__ feat,   // [NN][42]
                               const int* __restrict__ ptr,
                               const int* __restrict__ csr,
                               float4* __restrict__ z) {
    int n = blockIdx.x * (blockDim.x >> 5) + (threadIdx.x >> 5);
    if (n >= NN) return;
    const int lane = threadIdx.x & 31;
    const bool two = lane < 10;
    float4 a0 = __ldg(feat + (size_t)n * 42 + lane);
    float4 a1 = two ? __ldg(feat + (size_t)n * 42 + 32 + lane) : make_float4(0, 0, 0, 0);
    const int e0 = __ldg(ptr + n), e1 = __ldg(ptr + n + 1);
    for (int j = e0; j < e1; j++) {
        const size_t nb = (size_t)__ldg(csr + j) * 42;
        float4 v0 = __ldg(feat + nb + lane);
        a0.x += v0.x; a0.y += v0.y; a0.z += v0.z; a0.w += v0.w;
        if (two) {
            float4 v1 = __ldg(feat + nb + 32 + lane);
            a1.x += v1.x; a1.y += v1.y; a1.z += v1.z; a1.w += v1.w;
        }
    }
    z[(size_t)n * 42 + lane] = a0;
    if (two) z[(size_t)n * 42 + 32 + lane] = a1;
}

__global__ void gather2_kernel(const float4* __restrict__ feat,   // [NN][64]
                               const int* __restrict__ ptr,
                               const int* __restrict__ csr,
                               float4* __restrict__ z) {
    int n = blockIdx.x * (blockDim.x >> 5) + (threadIdx.x >> 5);
    if (n >= NN) return;
    const int lane = threadIdx.x & 31;
    float4 a0 = __ldg(feat + (size_t)n * 64 + lane);
    float4 a1 = __ldg(feat + (size_t)n * 64 + 32 + lane);
    const int e0 = __ldg(ptr + n), e1 = __ldg(ptr + n + 1);
    for (int j = e0; j < e1; j++) {
        const size_t nb = (size_t)__ldg(csr + j) * 64;
        float4 v0 = __ldg(feat + nb + lane);
        float4 v1 = __ldg(feat + nb + 32 + lane);
        a0.x += v0.x; a0.y += v0.y; a0.z += v0.z; a0.w += v0.w;
        a1.x += v1.x; a1.y += v1.y; a1.z += v1.z; a1.w += v1.w;
    }
    z[(size_t)n * 64 + lane] = a0;
    z[(size_t)n * 64 + 32 + lane] = a1;
}

// ---------------------------------------------------------------------------
// Weight prep: W[K,N] fp32 -> W^T split to bf16 hi/lo, [N][Kp], zero-padded.
// ---------------------------------------------------------------------------
__global__ void prep_w_kernel(const float* __restrict__ W,
                              __nv_bfloat16* __restrict__ hi,
                              __nv_bfloat16* __restrict__ lo,
                              int K, int N, int Kp) {
    int i = blockIdx.x * blockDim.x + threadIdx.x;
    if (i >= N * Kp) return;
    int n = i / Kp, k = i % Kp;
    float w = (k < K) ? __ldg(&W[(size_t)k * N + n]) : 0.f;
    __nv_bfloat16 h = __float2bfloat16(w);
    hi[i] = h;
    lo[i] = __float2bfloat16(w - __bfloat162float(h));
}

__global__ void init_out_kernel(float* __restrict__ out, const float* __restrict__ b2) {
    int i = blockIdx.x * blockDim.x + threadIdx.x;
    if (i < NN * 2) out[i] = __ldg(b2 + (i & 1));
}

// ---------------------------------------------------------------------------
// Warp-MMA bf16-split GEMM: CTA tile 128x128, 8 warps 4Mx2N, warp tile 32x64.
// OUTP: apply bias+relu then project onto w2 (256->2), atomicAdd into C[M][2].
// ---------------------------------------------------------------------------
#define SROW 72
#define SMAT (128 * SROW * 2)
#define OFF_AHI 0
#define OFF_ALO (SMAT)
#define OFF_BHI (2 * SMAT)
#define OFF_BLO (3 * SMAT)
#define SMTOT (4 * SMAT)           // 73728 B

template<bool RELU, bool OUTP>
__global__ __launch_bounds__(256)
void mma_gemm_kernel(const float* __restrict__ A, int lda,
                     const __nv_bfloat16* __restrict__ Bh,
                     const __nv_bfloat16* __restrict__ Bl, int Kp,
                     const float* __restrict__ bias,
                     float* __restrict__ C, int M,
                     const float* __restrict__ w2) {
    extern __shared__ __align__(16) char smem[];
    const uint32_t sb = smem_u32(smem);
    const int tid = threadIdx.x, wid = tid >> 5, lane = tid & 31;

    const int bm0 = blockIdx.y * 128;
    const int n0 = blockIdx.x * 128;

    const int arow = tid >> 1;
    const int acol0 = (tid & 1) * 32;
    const int mw = (wid >> 1) * 32;
    const int nw = (wid & 1) * 64;

    float acc[2][8][4];
#pragma unroll
    for (int ms = 0; ms < 2; ms++)
#pragma unroll
        for (int ns = 0; ns < 8; ns++)
#pragma unroll
            for (int q = 0; q < 4; q++) acc[ms][ns][q] = 0.f;

    const int l7 = lane & 7;
    const int aRowAdd = ((lane >> 3) & 1) * 8;
    const int aKAdd = (lane >> 4) * 8;
    const int bl = lane & 15;
    const int bRow = bl & 7;
    const int bKAdd = ((bl >> 3) & 1) * 8;

    const int nchunks = Kp >> 6;
    for (int ch = 0; ch < nchunks; ch++) {
        const int k0 = ch << 6;
        // ---- fill A hi/lo tile [128][64] (A rows 16B-aligned; overread hits
        //      zero-weight K-padding, values finite) ----
        {
            const int gRow = bm0 + arow;
            const bool ok = gRow < M;
            const uint32_t so = (uint32_t)(arow * SROW + acol0) * 2;
            const float4* p = (const float4*)(A + (size_t)(ok ? gRow : 0) * lda + k0 + acol0);
#pragma unroll
            for (int q = 0; q < 8; q++) {
                float4 v = ok ? __ldg(p + q) : make_float4(0, 0, 0, 0);
                float hx = __bfloat162float(__float2bfloat16(v.x));
                float hy = __bfloat162float(__float2bfloat16(v.y));
                float hz = __bfloat162float(__float2bfloat16(v.z));
                float hw = __bfloat162float(__float2bfloat16(v.w));
                *(uint32_t*)(smem + OFF_AHI + so + q * 8 + 0) = pack2(v.x, v.y);
                *(uint32_t*)(smem + OFF_AHI + so + q * 8 + 4) = pack2(v.z, v.w);
                *(uint32_t*)(smem + OFF_ALO + so + q * 8 + 0) = pack2(v.x - hx, v.y - hy);
                *(uint32_t*)(smem + OFF_ALO + so + q * 8 + 4) = pack2(v.z - hz, v.w - hw);
            }
        }
        // ---- fill B hi/lo tile from W^T [N][Kp] ----
        {
            const int gN = n0 + arow;
            const uint32_t so = (uint32_t)(arow * SROW + acol0) * 2;
            const uint4* ph = (const uint4*)(Bh + (size_t)gN * Kp + k0 + acol0);
            const uint4* pl = (const uint4*)(Bl + (size_t)gN * Kp + k0 + acol0);
#pragma unroll
            for (int q = 0; q < 4; q++) {
                *(uint4*)(smem + OFF_BHI + so + q * 16) = __ldg(ph + q);
                *(uint4*)(smem + OFF_BLO + so + q * 16) = __ldg(pl + q);
            }
        }
        __syncthreads();

#pragma unroll
        for (int kk = 0; kk < 64; kk += 16) {
            uint32_t ahi[2][4], alo[2][4], bhi[8][2], blo[8][2];
#pragma unroll
            for (int ms = 0; ms < 2; ms++) {
                uint32_t ra = sb + (uint32_t)((mw + ms * 16 + l7 + aRowAdd) * SROW + kk + aKAdd) * 2;
                ldm_x4(ahi[ms], ra + OFF_AHI);
                ldm_x4(alo[ms], ra + OFF_ALO);
            }
#pragma unroll
            for (int ns = 0; ns < 8; ns++) {
                uint32_t rb = sb + (uint32_t)((nw + ns * 8 + bRow) * SROW + kk + bKAdd) * 2;
                ldm_x2(bhi[ns], rb + OFF_BHI);
                ldm_x2(blo[ns], rb + OFF_BLO);
            }
#pragma unroll
            for (int ms = 0; ms < 2; ms++)
#pragma unroll
                for (int ns = 0; ns < 8; ns++) {
                    mma_bf16(acc[ms][ns], ahi[ms], bhi[ns]);
                    mma_bf16(acc[ms][ns], alo[ms], bhi[ns]);
                    mma_bf16(acc[ms][ns], ahi[ms], blo[ns]);
                }
        }
        __syncthreads();
    }

    const int r = lane >> 2;
    const int cp = (lane & 3) * 2;

    if (OUTP) {
        // bias + relu + project onto w2[256][2]; reduce over 4 lanes per row; atomicAdd.
        float s[2][2][2];   // [ms][rowhalf][outch]
#pragma unroll
        for (int ms = 0; ms < 2; ms++)
#pragma unroll
            for (int rh = 0; rh < 2; rh++) { s[ms][rh][0] = 0.f; s[ms][rh][1] = 0.f; }
#pragma unroll
        for (int ms = 0; ms < 2; ms++)
#pragma unroll
            for (int ns = 0; ns < 8; ns++) {
                const int col = n0 + nw + ns * 8 + cp;
                const float2 bb = *(const float2*)(bias + col);
                const float2 w0 = *(const float2*)(w2 + col * 2);
                const float2 w1 = *(const float2*)(w2 + (col + 1) * 2);
                float v0 = fmaxf(acc[ms][ns][0] + bb.x, 0.f);
                float v1 = fmaxf(acc[ms][ns][1] + bb.y, 0.f);
                float v2 = fmaxf(acc[ms][ns][2] + bb.x, 0.f);
                float v3 = fmaxf(acc[ms][ns][3] + bb.y, 0.f);
                s[ms][0][0] += v0 * w0.x + v1 * w1.x;
                s[ms][0][1] += v0 * w0.y + v1 * w1.y;
                s[ms][1][0] += v2 * w0.x + v3 * w1.x;
                s[ms][1][1] += v2 * w0.y + v3 * w1.y;
            }
#pragma unroll
        for (int ms = 0; ms < 2; ms++)
#pragma unroll
            for (int rh = 0; rh < 2; rh++)
#pragma unroll
                for (int oc = 0; oc < 2; oc++) {
                    float v = s[ms][rh][oc];
                    v += __shfl_xor_sync(0xffffffffu, v, 1);
                    v += __shfl_xor_sync(0xffffffffu, v, 2);
                    s[ms][rh][oc] = v;
                }
        if ((lane & 3) == 0) {
#pragma unroll
            for (int ms = 0; ms < 2; ms++)
#pragma unroll
                for (int rh = 0; rh < 2; rh++) {
                    const int row = bm0 + mw + ms * 16 + r + rh * 8;
                    if (row < M) {
                        atomicAdd(C + (size_t)row * 2 + 0, s[ms][rh][0]);
                        atomicAdd(C + (size_t)row * 2 + 1, s[ms][rh][1]);
                    }
                }
        }
    } else {
#pragma unroll
        for (int ms = 0; ms < 2; ms++)
#pragma unroll
            for (int ns = 0; ns < 8; ns++) {
                const int col = n0 + nw + ns * 8 + cp;
                const float2 bb = *(const float2*)(bias + col);
                const int row0 = bm0 + mw + ms * 16 + r;
                float2 o0, o1;
                o0.x = acc[ms][ns][0] + bb.x; o0.y = acc[ms][ns][1] + bb.y;
                o1.x = acc[ms][ns][2] + bb.x; o1.y = acc[ms][ns][3] + bb.y;
                if (RELU) {
                    o0.x = fmaxf(o0.x, 0.f); o0.y = fmaxf(o0.y, 0.f);
                    o1.x = fmaxf(o1.x, 0.f); o1.y = fmaxf(o1.y, 0.f);
                }
                if (row0 < M)     *(float2*)(C + (size_t)row0 * HID + col) = o0;
                if (row0 + 8 < M) *(float2*)(C + (size_t)(row0 + 8) * HID + col) = o1;
            }
    }
}

// ---------------------------------------------------------------------------
extern "C" void kernel_launch(void* const* d_in, const int* in_sizes, int n_in,
                              void* d_out, int out_size) {
    const float* x   = (const float*)d_in[0];
    const int*   ei  = (const int*)d_in[1];
    const float* W1a = (const float*)d_in[2];
    const float* b1a = (const float*)d_in[3];
    const float* W1b = (const float*)d_in[4];
    const float* b1b = (const float*)d_in[5];
    const float* W2a = (const float*)d_in[6];
    const float* b2a = (const float*)d_in[7];
    const float* W2b = (const float*)d_in[8];
    const float* b2b = (const float*)d_in[9];
    float* out = (float*)d_out;

    const int* src = ei;
    const int* dst = ei + NE;

    int *cnt, *ptr, *cursor, *csr;
    float *xp, *z1, *h1, *h, *z2;
    __nv_bfloat16 *w1ah, *w1al, *w1bh, *w1bl, *w2ah, *w2al;
    cudaGetSymbolAddress((void**)&cnt,    g_cnt);
    cudaGetSymbolAddress((void**)&ptr,    g_ptr);
    cudaGetSymbolAddress((void**)&cursor, g_cursor);
    cudaGetSymbolAddress((void**)&csr,    g_csr);
    cudaGetSymbolAddress((void**)&xp,     g_xp);
    cudaGetSymbolAddress((void**)&z1,     g_z1);
    cudaGetSymbolAddress((void**)&h1,     g_h1);
    cudaGetSymbolAddress((void**)&h,      g_h);
    cudaGetSymbolAddress((void**)&z2,     g_z2);
    cudaGetSymbolAddress((void**)&w1ah,   g_w1a_hi);
    cudaGetSymbolAddress((void**)&w1al,   g_w1a_lo);
    cudaGetSymbolAddress((void**)&w1bh,   g_w1b_hi);
    cudaGetSymbolAddress((void**)&w1bl,   g_w1b_lo);
    cudaGetSymbolAddress((void**)&w2ah,   g_w2a_hi);
    cudaGetSymbolAddress((void**)&w2al,   g_w2a_lo);

    cudaFuncSetAttribute(mma_gemm_kernel<true, false>,
                         cudaFuncAttributeMaxDynamicSharedMemorySize, SMTOT);
    cudaFuncSetAttribute(mma_gemm_kernel<true, true>,
                         cudaFuncAttributeMaxDynamicSharedMemorySize, SMTOT);

    const dim3 gemmGrid(2, (NN + 127) / 128);
    const int edgeGrid = (NE + 255) / 256;
    const int nodeGrid = (NN + 7) / 8;

    // ---- CSR build + padded x (independent of weights) ----
    cudaMemsetAsync(cnt, 0, sizeof(int) * NN);
    hist_kernel<<<edgeGrid, 256>>>(dst, cnt);
    copy_pad_kernel<<<(NN * XP_LD + 255) / 256, 256>>>(x, xp);
    scan_kernel<<<1, 1024>>>(cnt, ptr, cursor);
    fill_kernel<<<edgeGrid, 256>>>(src, dst, cursor, csr);

    // ---- weight prep ----
    prep_w_kernel<<<(HID * KP1 + 255) / 256, 256>>>(W1a, w1ah, w1al, INC, HID, KP1);
    prep_w_kernel<<<(HID * HID + 255) / 256, 256>>>(W1b, w1bh, w1bl, HID, HID, HID);
    prep_w_kernel<<<(HID * HID + 255) / 256, 256>>>(W2a, w2ah, w2al, HID, HID, HID);

    // ---- layer 1 ----
    gather1_kernel<<<nodeGrid, 256>>>((const float4*)xp, ptr, csr, (float4*)z1);
    mma_gemm_kernel<true, false><<<gemmGrid, 256, SMTOT>>>(
        z1, XP_LD, w1ah, w1al, KP1, b1a, h1, NN, nullptr);
    mma_gemm_kernel<true, false><<<gemmGrid, 256, SMTOT>>>(
        h1, HID, w1bh, w1bl, HID, b1b, h, NN, nullptr);

    // ---- layer 2 ----
    gather2_kernel<<<nodeGrid, 256>>>((const float4*)h, ptr, csr, (float4*)z2);
    init_out_kernel<<<(NN * 2 + 255) / 256, 256>>>(out, b2b);
    mma_gemm_kernel<true, true><<<gemmGrid, 256, SMTOT>>>(
        z2, HID, w2ah, w2al, HID, b2a, out, NN, W2b);
}